// round 14
// baseline (speedup 1.0000x reference)
#include <cuda_runtime.h>
#include <cuda_bf16.h>
#include <cuda_fp16.h>
#include <cstdint>

#define N_USER 50000
#define N_ITEM 50000
#define N_NODES 100000
#define NNZ 3200000
#define EMB 64
#define N_LAYERS 3
#define BATCH 4096
#define OUT_EMB 256           // EMB * (N_LAYERS + 1)
#define ELL_CAP 96            // Poisson(32): P(deg>=96) ~ 3e-19 per row
#define KT 16                 // K-tile for dense phase
#define DROWS 256             // rows per fused block
#define SROW_STRIDE 68        // side smem row stride (floats): 16B-aligned rows

// dynamic smem layout (bytes)
#define OFF_SROW   0
#define SZ_SROW    (DROWS * SROW_STRIDE * 4)          // 69632
#define OFF_SS     (OFF_SROW + SZ_SROW)
#define SZ_SS      (KT * DROWS * 4)                   // 16384
#define OFF_SP     (OFF_SS + SZ_SS)
#define SZ_SP      (KT * DROWS * 4)                   // 16384
#define OFF_SWG    (OFF_SP + SZ_SP)
#define SZ_SW      (KT * EMB * 4)                     // 4096
#define OFF_SWB    (OFF_SWG + SZ_SW)
#define SMEM_BYTES (OFF_SWB + SZ_SW)                  // 110592

typedef unsigned long long u64t;

// Scratch (no cudaMalloc allowed): __device__ globals.
__device__ float  g_ego[N_NODES * EMB];       // fp32 embeddings (dense input)
// DOUBLE-BUFFERED fp16 mirror: layer k gathers buf[k&1], writes buf[(k+1)&1].
// (Single buffer raced: other blocks' epilogues overwrite rows mid-gather.)
__device__ __half g_ego_h[2][N_NODES * EMB];
__device__ float  g_all[N_NODES * OUT_EMB];   // [ego0 | n1 | n2 | n3]
__device__ int    g_cnt[N_NODES];             // per-row degree (built once)
__device__ int2   g_ell[(size_t)N_NODES * ELL_CAP]; // padded {col*EMB, val_bits}

// ---------------------------------------------------------------------------
// packed f32x2 helpers (sm_103a FFMA2 — only reachable via PTX)
// ---------------------------------------------------------------------------
__device__ __forceinline__ u64t ffma2(u64t a, u64t b, u64t c) {
    u64t d;
    asm("fma.rn.f32x2 %0, %1, %2, %3;" : "=l"(d) : "l"(a), "l"(b), "l"(c));
    return d;
}
__device__ __forceinline__ u64t pack2(float x) {
    u64t d;
    asm("mov.b64 %0, {%1, %1};" : "=l"(d) : "f"(x));
    return d;
}
__device__ __forceinline__ float2 unpack2(u64t d) {
    float2 f;
    asm("mov.b64 {%0, %1}, %2;" : "=f"(f.x), "=f"(f.y) : "l"(d));
    return f;
}

// ---------------------------------------------------------------------------
// Init: ego = concat(user_emb, item_emb) (fp32 + fp16 buffer 0);
// all[:, 0:64] = ego; zero degrees.
// ---------------------------------------------------------------------------
__global__ __launch_bounds__(256) void k_init(const float* __restrict__ ue,
                                              const float* __restrict__ ie) {
    int idx = blockIdx.x * blockDim.x + threadIdx.x;   // float4 index
    const int total = N_NODES * EMB / 4;
    if (idx >= total) return;
    if (idx < N_NODES) g_cnt[idx] = 0;
    int r = idx >> 4;          // row (EMB/4 = 16 float4 per row)
    int c = idx & 15;
    float4 v = (r < N_USER)
        ? reinterpret_cast<const float4*>(ue)[(size_t)r * 16 + c]
        : reinterpret_cast<const float4*>(ie)[(size_t)(r - N_USER) * 16 + c];
    reinterpret_cast<float4*>(g_ego)[idx] = v;
    __half2* hp = reinterpret_cast<__half2*>(g_ego_h[0]);
    hp[idx * 2]     = __floats2half2_rn(v.x, v.y);
    hp[idx * 2 + 1] = __floats2half2_rn(v.z, v.w);
    *reinterpret_cast<float4*>(&g_all[(size_t)r * OUT_EMB + c * 4]) = v;
}

// ---------------------------------------------------------------------------
// ELL build: single pass, no scan. Stores col*EMB (element offset) directly.
// ---------------------------------------------------------------------------
__global__ __launch_bounds__(256) void k_build(const int* __restrict__ arow,
                                               const int* __restrict__ acol,
                                               const float* __restrict__ aval) {
    int e = blockIdx.x * blockDim.x + threadIdx.x;
    if (e >= NNZ) return;
    int r = arow[e];
    int pos = atomicAdd(&g_cnt[r], 1);
    if (pos < ELL_CAP)
        g_ell[(size_t)r * ELL_CAP + pos] =
            make_int2(acol[e] * EMB, __float_as_int(aval[e]));
}

// ---------------------------------------------------------------------------
// FUSED layer kernel: phase 1 = ELL SpMM into smem (side), phase 2 = dense.
//   ego_new = leaky( side@Wg + bg + (ego*side)@Wb + bb )
//   g_ego / g_ego_h[out] <- ego_new;  g_all slice <- ego_new/||.||
// 256 threads, 256 rows/block. Dense thread = 8 rows x 8 cols, f32x2 acc.
// ---------------------------------------------------------------------------
__global__ __launch_bounds__(256, 2) void k_layer(const float* __restrict__ Wg,
                                                  const float* __restrict__ bg,
                                                  const float* __restrict__ Wb,
                                                  const float* __restrict__ bb,
                                                  int layer) {
    extern __shared__ char smem[];
    float* sRow = reinterpret_cast<float*>(smem + OFF_SROW); // [DROWS][68]
    float* sS   = reinterpret_cast<float*>(smem + OFF_SS);   // [KT][DROWS]
    float* sP   = reinterpret_cast<float*>(smem + OFF_SP);   // [KT][DROWS]
    float* sWg  = reinterpret_cast<float*>(smem + OFF_SWG);  // [KT][EMB]
    float* sWb  = reinterpret_cast<float*>(smem + OFF_SWB);  // [KT][EMB]
    int2*  se   = reinterpret_cast<int2*>(smem + OFF_SS);    // phase-1 alias

    const int tid  = threadIdx.x;
    const int lane = tid & 31;
    const int wid  = tid >> 5;
    const int row_base = blockIdx.x * DROWS;
    const __half* __restrict__ ego_in = g_ego_h[layer & 1];
    __half* __restrict__ ego_out = g_ego_h[(layer + 1) & 1];

    // ================= Phase 1: SpMM into sRow =================
    {
        int2* sew = se + wid * 32;
        for (int rr = 0; rr < 32; rr++) {
            int lrow = wid * 32 + rr;
            int grow = row_base + lrow;
            float2 acc = make_float2(0.f, 0.f);
            if (grow < N_NODES) {
                int cnt = g_cnt[grow];
                if (cnt > ELL_CAP) cnt = ELL_CAP;
                const int2* row = &g_ell[(size_t)grow * ELL_CAP];
                for (int base = 0; base < cnt; base += 32) {
                    int idx = base + lane;
                    int2 ev = make_int2(0, 0);
                    if (idx < cnt) ev = row[idx];
                    sew[lane] = ev;
                    __syncwarp();
                    int n = cnt - base; if (n > 32) n = 32;
                    #pragma unroll 4
                    for (int j = 0; j < n; j++) {
                        int2 e2 = sew[j];
                        float val = __int_as_float(e2.y);
                        __half2 h = *reinterpret_cast<const __half2*>(
                            &ego_in[(size_t)e2.x + lane * 2]);
                        float2 x = __half22float2(h);
                        acc.x = fmaf(val, x.x, acc.x);
                        acc.y = fmaf(val, x.y, acc.y);
                    }
                    __syncwarp();
                }
            }
            *reinterpret_cast<float2*>(&sRow[lrow * SROW_STRIDE + lane * 2]) = acc;
        }
    }
    __syncthreads();

    // ================= Phase 2: dense (R9 structure) =================
    const int jt   = lane & 7;        // col-group 0..7 (8 cols each)
    const int slot = lane >> 3;       // 0..3 (8 rows each)
    const int lrow0 = wid * 32 + slot * 8;

    const float* Wgk = Wg + (size_t)layer * EMB * EMB;
    const float* Wbk = Wb + (size_t)layer * EMB * EMB;

    u64t acc[4][8];
    {   // bias seed from global (uniform per-jt addresses -> L1 broadcast)
        const float4* bg4 = reinterpret_cast<const float4*>(bg + layer * EMB);
        const float4* bb4 = reinterpret_cast<const float4*>(bb + layer * EMB);
        float4 b0 = bg4[jt * 2],     b1 = bg4[jt * 2 + 1];
        float4 c0 = bb4[jt * 2],     c1 = bb4[jt * 2 + 1];
        float bsum[8] = {b0.x + c0.x, b0.y + c0.y, b0.z + c0.z, b0.w + c0.w,
                         b1.x + c1.x, b1.y + c1.y, b1.z + c1.z, b1.w + c1.w};
        #pragma unroll
        for (int c = 0; c < 8; c++) {
            u64t bp = pack2(bsum[c]);
            #pragma unroll
            for (int rp = 0; rp < 4; rp++) acc[rp][c] = bp;
        }
    }

    const int crow = min(row_base + tid, N_NODES - 1);   // ego row (clamped)

    for (int kt = 0; kt < EMB / KT; kt++) {
        // --- stage W tile [KT][64]: one float4 per thread per matrix ---
        {
            int i_l = tid >> 4, c4 = tid & 15;
            size_t g = (size_t)(kt * KT + i_l) * EMB + c4 * 4;
            float4 wgv = *reinterpret_cast<const float4*>(&Wgk[g]);
            float4 wbv = *reinterpret_cast<const float4*>(&Wbk[g]);
            *reinterpret_cast<float4*>(&sWg[i_l * EMB + c4 * 4]) = wgv;
            *reinterpret_cast<float4*>(&sWb[i_l * EMB + c4 * 4]) = wbv;
        }
        // --- stage s/p transposed: side from sRow (LDS), ego from global ---
        #pragma unroll
        for (int q = 0; q < KT / 4; q++) {
            float4 sv = *reinterpret_cast<const float4*>(
                &sRow[tid * SROW_STRIDE + kt * KT + q * 4]);
            float4 ev = *reinterpret_cast<const float4*>(
                &g_ego[(size_t)crow * EMB + kt * KT + q * 4]);
            sS[(q * 4 + 0) * DROWS + tid] = sv.x;
            sS[(q * 4 + 1) * DROWS + tid] = sv.y;
            sS[(q * 4 + 2) * DROWS + tid] = sv.z;
            sS[(q * 4 + 3) * DROWS + tid] = sv.w;
            sP[(q * 4 + 0) * DROWS + tid] = sv.x * ev.x;
            sP[(q * 4 + 1) * DROWS + tid] = sv.y * ev.y;
            sP[(q * 4 + 2) * DROWS + tid] = sv.z * ev.z;
            sP[(q * 4 + 3) * DROWS + tid] = sv.w * ev.w;
        }
        __syncthreads();

        #pragma unroll
        for (int i = 0; i < KT; i++) {
            ulonglong2 sA  = *reinterpret_cast<const ulonglong2*>(&sS[i * DROWS + lrow0]);
            ulonglong2 sB2 = *reinterpret_cast<const ulonglong2*>(&sS[i * DROWS + lrow0 + 4]);
            ulonglong2 pA  = *reinterpret_cast<const ulonglong2*>(&sP[i * DROWS + lrow0]);
            ulonglong2 pB2 = *reinterpret_cast<const ulonglong2*>(&sP[i * DROWS + lrow0 + 4]);
            u64t s2[4] = {sA.x, sA.y, sB2.x, sB2.y};
            u64t p2[4] = {pA.x, pA.y, pB2.x, pB2.y};

            float4 wg0 = *reinterpret_cast<const float4*>(&sWg[i * EMB + jt * 8]);
            float4 wg1 = *reinterpret_cast<const float4*>(&sWg[i * EMB + jt * 8 + 4]);
            float4 wb0 = *reinterpret_cast<const float4*>(&sWb[i * EMB + jt * 8]);
            float4 wb1 = *reinterpret_cast<const float4*>(&sWb[i * EMB + jt * 8 + 4]);
            float wgf[8] = {wg0.x, wg0.y, wg0.z, wg0.w, wg1.x, wg1.y, wg1.z, wg1.w};
            float wbf[8] = {wb0.x, wb0.y, wb0.z, wb0.w, wb1.x, wb1.y, wb1.z, wb1.w};

            #pragma unroll
            for (int c = 0; c < 8; c++) {
                u64t wgp = pack2(wgf[c]);
                u64t wbp = pack2(wbf[c]);
                #pragma unroll
                for (int rp = 0; rp < 4; rp++) {
                    acc[rp][c] = ffma2(s2[rp], wgp, acc[rp][c]);
                    acc[rp][c] = ffma2(p2[rp], wbp, acc[rp][c]);
                }
            }
        }
        __syncthreads();
    }

    // --- epilogue: leaky + row-norm (8-lane shfl) + stores, 2 rows per rp ---
    #pragma unroll
    for (int rp = 0; rp < 4; rp++) {
        float a0[8], a1[8];
        #pragma unroll
        for (int c = 0; c < 8; c++) {
            float2 u = unpack2(acc[rp][c]);
            a0[c] = u.x;
            a1[c] = u.y;
        }
        float n0 = 0.f, n1 = 0.f;
        #pragma unroll
        for (int c = 0; c < 8; c++) {
            float v0 = a0[c]; v0 = (v0 > 0.f) ? v0 : 0.2f * v0; a0[c] = v0; n0 += v0 * v0;
            float v1 = a1[c]; v1 = (v1 > 0.f) ? v1 : 0.2f * v1; a1[c] = v1; n1 += v1 * v1;
        }
        #pragma unroll
        for (int m = 1; m < 8; m <<= 1) {
            n0 += __shfl_xor_sync(0xffffffffu, n0, m, 8);
            n1 += __shfl_xor_sync(0xffffffffu, n1, m, 8);
        }
        float inv0 = 1.0f / fmaxf(sqrtf(n0), 1e-12f);
        float inv1 = 1.0f / fmaxf(sqrtf(n1), 1e-12f);

        int grow0 = row_base + lrow0 + rp * 2;
        if (grow0 < N_NODES) {
            float* egp = &g_ego[(size_t)grow0 * EMB + jt * 8];
            reinterpret_cast<float4*>(egp)[0] = make_float4(a0[0], a0[1], a0[2], a0[3]);
            reinterpret_cast<float4*>(egp)[1] = make_float4(a0[4], a0[5], a0[6], a0[7]);
            __half2* hp = reinterpret_cast<__half2*>(&ego_out[(size_t)grow0 * EMB + jt * 8]);
            hp[0] = __floats2half2_rn(a0[0], a0[1]);
            hp[1] = __floats2half2_rn(a0[2], a0[3]);
            hp[2] = __floats2half2_rn(a0[4], a0[5]);
            hp[3] = __floats2half2_rn(a0[6], a0[7]);
            float* alp = &g_all[(size_t)grow0 * OUT_EMB + (layer + 1) * EMB + jt * 8];
            reinterpret_cast<float4*>(alp)[0] =
                make_float4(a0[0] * inv0, a0[1] * inv0, a0[2] * inv0, a0[3] * inv0);
            reinterpret_cast<float4*>(alp)[1] =
                make_float4(a0[4] * inv0, a0[5] * inv0, a0[6] * inv0, a0[7] * inv0);
        }
        int grow1 = grow0 + 1;
        if (grow1 < N_NODES) {
            float* egp = &g_ego[(size_t)grow1 * EMB + jt * 8];
            reinterpret_cast<float4*>(egp)[0] = make_float4(a1[0], a1[1], a1[2], a1[3]);
            reinterpret_cast<float4*>(egp)[1] = make_float4(a1[4], a1[5], a1[6], a1[7]);
            __half2* hp = reinterpret_cast<__half2*>(&ego_out[(size_t)grow1 * EMB + jt * 8]);
            hp[0] = __floats2half2_rn(a1[0], a1[1]);
            hp[1] = __floats2half2_rn(a1[2], a1[3]);
            hp[2] = __floats2half2_rn(a1[4], a1[5]);
            hp[3] = __floats2half2_rn(a1[6], a1[7]);
            float* alp = &g_all[(size_t)grow1 * OUT_EMB + (layer + 1) * EMB + jt * 8];
            reinterpret_cast<float4*>(alp)[0] =
                make_float4(a1[0] * inv1, a1[1] * inv1, a1[2] * inv1, a1[3] * inv1);
            reinterpret_cast<float4*>(alp)[1] =
                make_float4(a1[4] * inv1, a1[5] * inv1, a1[6] * inv1, a1[7] * inv1);
        }
    }
}

// ---------------------------------------------------------------------------
// Final gather: out = [ all[users], all[N_USER+pos], all[N_USER+neg] ]
// ---------------------------------------------------------------------------
__global__ __launch_bounds__(256) void k_gather(const int* __restrict__ users,
                                                const int* __restrict__ pos,
                                                const int* __restrict__ neg,
                                                float* __restrict__ out) {
    int t = blockIdx.x * blockDim.x + threadIdx.x;
    const int total = 3 * BATCH * (OUT_EMB / 4);
    if (t >= total) return;
    int g = t / (BATCH * (OUT_EMB / 4));
    int rem = t - g * (BATCH * (OUT_EMB / 4));
    int b = rem >> 6;          // OUT_EMB/4 = 64 float4 per row
    int f = rem & 63;
    int src;
    if (g == 0)      src = users[b];
    else if (g == 1) src = N_USER + pos[b];
    else             src = N_USER + neg[b];
    reinterpret_cast<float4*>(out)[t] =
        reinterpret_cast<const float4*>(&g_all[(size_t)src * OUT_EMB])[f];
}

// ---------------------------------------------------------------------------
extern "C" void kernel_launch(void* const* d_in, const int* in_sizes, int n_in,
                              void* d_out, int out_size) {
    const int*   users = (const int*)   d_in[0];
    const int*   pos   = (const int*)   d_in[1];
    const int*   neg   = (const int*)   d_in[2];
    const int*   arow  = (const int*)   d_in[3];
    const int*   acol  = (const int*)   d_in[4];
    const float* aval  = (const float*) d_in[5];
    const float* ue    = (const float*) d_in[6];
    const float* ie    = (const float*) d_in[7];
    const float* Wg    = (const float*) d_in[8];
    const float* bg    = (const float*) d_in[9];
    const float* Wb    = (const float*) d_in[10];
    const float* bb    = (const float*) d_in[11];
    float* out = (float*)d_out;

    cudaFuncSetAttribute(k_layer,
                         cudaFuncAttributeMaxDynamicSharedMemorySize, SMEM_BYTES);

    k_init<<<(N_NODES * EMB / 4 + 255) / 256, 256>>>(ue, ie);
    k_build<<<(NNZ + 255) / 256, 256>>>(arow, acol, aval);

    const int grid = (N_NODES + DROWS - 1) / DROWS;
    for (int k = 0; k < N_LAYERS; k++)
        k_layer<<<grid, 256, SMEM_BYTES>>>(Wg, bg, Wb, bb, k);

    k_gather<<<(3 * BATCH * (OUT_EMB / 4) + 255) / 256, 256>>>(users, pos, neg, out);
}

// round 15
// speedup vs baseline: 1.9859x; 1.9859x over previous
#include <cuda_runtime.h>
#include <cuda_bf16.h>
#include <cstdint>

#define N_USER 50000
#define N_ITEM 50000
#define N_NODES 100000
#define NNZ 3200000
#define EMB 64
#define N_LAYERS 3
#define BATCH 4096
#define OUT_EMB 256           // EMB * (N_LAYERS + 1)
#define ELL_CAP 96            // Poisson(32): P(deg>=96) ~ 3e-19 per row
#define KT 16                 // K-tile for dense
#define DROWS 256             // rows per dense block

typedef unsigned long long u64t;

// Scratch (no cudaMalloc allowed): __device__ globals.
__device__ float g_ego[N_NODES * EMB];        // current (unnormalized) embeddings
__device__ float g_side[N_NODES * EMB];       // SpMM result
__device__ float g_all[N_NODES * OUT_EMB];    // [ego0 | n1 | n2 | n3]
__device__ int   g_cnt[N_NODES];              // per-row degree (built once)
__device__ int2  g_ell[(size_t)N_NODES * ELL_CAP]; // padded {col*EMB, val_bits}

// ---------------------------------------------------------------------------
// packed f32x2 helpers (sm_103a FFMA2 — only reachable via PTX)
// ---------------------------------------------------------------------------
__device__ __forceinline__ u64t ffma2(u64t a, u64t b, u64t c) {
    u64t d;
    asm("fma.rn.f32x2 %0, %1, %2, %3;" : "=l"(d) : "l"(a), "l"(b), "l"(c));
    return d;
}
__device__ __forceinline__ u64t pack2(float x) {
    u64t d;
    asm("mov.b64 %0, {%1, %1};" : "=l"(d) : "f"(x));
    return d;
}
__device__ __forceinline__ float2 unpack2(u64t d) {
    float2 f;
    asm("mov.b64 {%0, %1}, %2;" : "=f"(f.x), "=f"(f.y) : "l"(d));
    return f;
}

// ---------------------------------------------------------------------------
// Init: ego = concat(user_emb, item_emb); all[:, 0:64] = ego; zero degrees.
// ---------------------------------------------------------------------------
__global__ __launch_bounds__(256) void k_init(const float* __restrict__ ue,
                                              const float* __restrict__ ie) {
    int idx = blockIdx.x * blockDim.x + threadIdx.x;   // float4 index
    const int total = N_NODES * EMB / 4;
    if (idx >= total) return;
    if (idx < N_NODES) g_cnt[idx] = 0;
    int r = idx >> 4;          // row (EMB/4 = 16 float4 per row)
    int c = idx & 15;
    float4 v = (r < N_USER)
        ? reinterpret_cast<const float4*>(ue)[(size_t)r * 16 + c]
        : reinterpret_cast<const float4*>(ie)[(size_t)(r - N_USER) * 16 + c];
    reinterpret_cast<float4*>(g_ego)[idx] = v;
    *reinterpret_cast<float4*>(&g_all[(size_t)r * OUT_EMB + c * 4]) = v;
}

// ---------------------------------------------------------------------------
// ELL build: single pass, no scan. Stores col*EMB (element offset) directly.
// ---------------------------------------------------------------------------
__global__ __launch_bounds__(256) void k_build(const int* __restrict__ arow,
                                               const int* __restrict__ acol,
                                               const float* __restrict__ aval) {
    int e = blockIdx.x * blockDim.x + threadIdx.x;
    if (e >= NNZ) return;
    int r = arow[e];
    int pos = atomicAdd(&g_cnt[r], 1);
    if (pos < ELL_CAP)
        g_ell[(size_t)r * ELL_CAP + pos] =
            make_int2(acol[e] * EMB, __float_as_int(aval[e]));
}

// ---------------------------------------------------------------------------
// ELL SpMM: one warp per row, 2 edges in flight per step.
// Half-warp h (lane>>4) processes edge 2j+h; lane covers dims [4*(lane&15)..+4)
// via LDG.128. Per 2 edges: 1 LDS + 1 LDG.128 + 4 FFMA (was 8 issues).
// Final: shfl_xor(16) combine, half-warp float4 store.
// ---------------------------------------------------------------------------
__global__ __launch_bounds__(256) void k_spmm_ell() {
    __shared__ int2 se[8][32];
    int gw = (blockIdx.x * 256 + threadIdx.x) >> 5;   // uniform within warp
    if (gw >= N_NODES) return;
    int lane = threadIdx.x & 31;
    int wl = threadIdx.x >> 5;
    int h = lane >> 4;          // half-warp: which edge of the pair
    int q = lane & 15;          // dim quad within the row
    int cnt = g_cnt[gw];
    if (cnt > ELL_CAP) cnt = ELL_CAP;
    const int2* row = &g_ell[(size_t)gw * ELL_CAP];
    float4 acc = make_float4(0.f, 0.f, 0.f, 0.f);
    for (int base = 0; base < cnt; base += 32) {
        int idx = base + lane;
        int2 ev = make_int2(0, 0);                     // val=0 pad: no-op edge
        if (idx < cnt) ev = row[idx];
        se[wl][lane] = ev;
        __syncwarp();
        int n = cnt - base; if (n > 32) n = 32;
        int steps = (n + 1) >> 1;
        #pragma unroll 4
        for (int j = 0; j < steps; j++) {
            int2 e2 = se[wl][2 * j + h];
            float val = __int_as_float(e2.y);
            float4 x = *reinterpret_cast<const float4*>(
                &g_ego[(size_t)e2.x + q * 4]);
            acc.x = fmaf(val, x.x, acc.x);
            acc.y = fmaf(val, x.y, acc.y);
            acc.z = fmaf(val, x.z, acc.z);
            acc.w = fmaf(val, x.w, acc.w);
        }
        __syncwarp();
    }
    // combine the two half-warp partials (edge-even + edge-odd)
    acc.x += __shfl_xor_sync(0xffffffffu, acc.x, 16);
    acc.y += __shfl_xor_sync(0xffffffffu, acc.y, 16);
    acc.z += __shfl_xor_sync(0xffffffffu, acc.z, 16);
    acc.w += __shfl_xor_sync(0xffffffffu, acc.w, 16);
    if (h == 0)
        *reinterpret_cast<float4*>(&g_side[(size_t)gw * EMB + q * 4]) = acc;
}

// ---------------------------------------------------------------------------
// Dense layer: ego_new = leaky( side@Wg + bg + (ego*side)@Wb + bb )
// 256 threads, 256 rows/block. Thread = 8 rows x 8 cols, row-pair-packed acc.
// (R9 version — best measured at 64.3us/layer.)
// ---------------------------------------------------------------------------
__global__ __launch_bounds__(256, 2) void k_dense(const float* __restrict__ Wg,
                                                  const float* __restrict__ bg,
                                                  const float* __restrict__ Wb,
                                                  const float* __restrict__ bb,
                                                  int layer) {
    __shared__ float sWg[KT * EMB];        // 4KB
    __shared__ float sWb[KT * EMB];        // 4KB
    __shared__ float sS[KT * DROWS];       // 16KB  sS[i][row]
    __shared__ float sP[KT * DROWS];       // 16KB  sP[i][row]

    const int tid  = threadIdx.x;
    const int lane = tid & 31;
    const int wid  = tid >> 5;
    const int jt   = lane & 7;        // col-group 0..7 (8 cols each)
    const int slot = lane >> 3;       // 0..3 (8 rows each)
    const int lrow0 = wid * 32 + slot * 8;     // first of this thread's 8 rows
    const int row_base = blockIdx.x * DROWS;

    const float* Wgk = Wg + (size_t)layer * EMB * EMB;
    const float* Wbk = Wb + (size_t)layer * EMB * EMB;

    // acc[rp][c]: f32x2 = rows (lrow0+2rp, lrow0+2rp+1), col jt*8+c.
    u64t acc[4][8];
    {   // bias seed from global (uniform per-jt addresses -> L1 broadcast)
        const float4* bg4 = reinterpret_cast<const float4*>(bg + layer * EMB);
        const float4* bb4 = reinterpret_cast<const float4*>(bb + layer * EMB);
        float4 b0 = bg4[jt * 2],     b1 = bg4[jt * 2 + 1];
        float4 c0 = bb4[jt * 2],     c1 = bb4[jt * 2 + 1];
        float bsum[8] = {b0.x + c0.x, b0.y + c0.y, b0.z + c0.z, b0.w + c0.w,
                         b1.x + c1.x, b1.y + c1.y, b1.z + c1.z, b1.w + c1.w};
        #pragma unroll
        for (int c = 0; c < 8; c++) {
            u64t bp = pack2(bsum[c]);
            #pragma unroll
            for (int rp = 0; rp < 4; rp++) acc[rp][c] = bp;
        }
    }

    // staging role: this thread stages global row (row_base + tid), clamped
    const int crow = min(row_base + tid, N_NODES - 1);

    for (int kt = 0; kt < EMB / KT; kt++) {
        // --- stage W tile [KT][64]: one float4 per thread per matrix ---
        {
            int i_l = tid >> 4, c4 = tid & 15;
            size_t g = (size_t)(kt * KT + i_l) * EMB + c4 * 4;
            float4 wgv = *reinterpret_cast<const float4*>(&Wgk[g]);
            float4 wbv = *reinterpret_cast<const float4*>(&Wbk[g]);
            *reinterpret_cast<float4*>(&sWg[i_l * EMB + c4 * 4]) = wgv;
            *reinterpret_cast<float4*>(&sWb[i_l * EMB + c4 * 4]) = wbv;
        }
        // --- stage s/p transposed: row = tid, dims kt*KT..+KT ---
        #pragma unroll
        for (int q = 0; q < KT / 4; q++) {
            size_t g = (size_t)crow * EMB + kt * KT + q * 4;
            float4 sv = *reinterpret_cast<const float4*>(&g_side[g]);
            float4 ev = *reinterpret_cast<const float4*>(&g_ego[g]);
            sS[(q * 4 + 0) * DROWS + tid] = sv.x;
            sS[(q * 4 + 1) * DROWS + tid] = sv.y;
            sS[(q * 4 + 2) * DROWS + tid] = sv.z;
            sS[(q * 4 + 3) * DROWS + tid] = sv.w;
            sP[(q * 4 + 0) * DROWS + tid] = sv.x * ev.x;
            sP[(q * 4 + 1) * DROWS + tid] = sv.y * ev.y;
            sP[(q * 4 + 2) * DROWS + tid] = sv.z * ev.z;
            sP[(q * 4 + 3) * DROWS + tid] = sv.w * ev.w;
        }
        __syncthreads();

        #pragma unroll
        for (int i = 0; i < KT; i++) {
            // s/p row pairs straight from LDS.128 (no packing)
            ulonglong2 sA  = *reinterpret_cast<const ulonglong2*>(&sS[i * DROWS + lrow0]);
            ulonglong2 sB2 = *reinterpret_cast<const ulonglong2*>(&sS[i * DROWS + lrow0 + 4]);
            ulonglong2 pA  = *reinterpret_cast<const ulonglong2*>(&sP[i * DROWS + lrow0]);
            ulonglong2 pB2 = *reinterpret_cast<const ulonglong2*>(&sP[i * DROWS + lrow0 + 4]);
            u64t s2[4] = {sA.x, sA.y, sB2.x, sB2.y};
            u64t p2[4] = {pA.x, pA.y, pB2.x, pB2.y};

            // W scalars for this thread's 8 cols
            float4 wg0 = *reinterpret_cast<const float4*>(&sWg[i * EMB + jt * 8]);
            float4 wg1 = *reinterpret_cast<const float4*>(&sWg[i * EMB + jt * 8 + 4]);
            float4 wb0 = *reinterpret_cast<const float4*>(&sWb[i * EMB + jt * 8]);
            float4 wb1 = *reinterpret_cast<const float4*>(&sWb[i * EMB + jt * 8 + 4]);
            float wgf[8] = {wg0.x, wg0.y, wg0.z, wg0.w, wg1.x, wg1.y, wg1.z, wg1.w};
            float wbf[8] = {wb0.x, wb0.y, wb0.z, wb0.w, wb1.x, wb1.y, wb1.z, wb1.w};

            #pragma unroll
            for (int c = 0; c < 8; c++) {
                u64t wgp = pack2(wgf[c]);
                u64t wbp = pack2(wbf[c]);
                #pragma unroll
                for (int rp = 0; rp < 4; rp++) {
                    acc[rp][c] = ffma2(s2[rp], wgp, acc[rp][c]);
                    acc[rp][c] = ffma2(p2[rp], wbp, acc[rp][c]);
                }
            }
        }
        __syncthreads();
    }

    // --- epilogue: leaky + row-norm (8-lane shfl) + stores, 2 rows per rp ---
    #pragma unroll
    for (int rp = 0; rp < 4; rp++) {
        float a0[8], a1[8];            // row lrow0+2rp, row lrow0+2rp+1
        #pragma unroll
        for (int c = 0; c < 8; c++) {
            float2 u = unpack2(acc[rp][c]);
            a0[c] = u.x;
            a1[c] = u.y;
        }
        float n0 = 0.f, n1 = 0.f;
        #pragma unroll
        for (int c = 0; c < 8; c++) {
            float v0 = a0[c]; v0 = (v0 > 0.f) ? v0 : 0.2f * v0; a0[c] = v0; n0 += v0 * v0;
            float v1 = a1[c]; v1 = (v1 > 0.f) ? v1 : 0.2f * v1; a1[c] = v1; n1 += v1 * v1;
        }
        #pragma unroll
        for (int m = 1; m < 8; m <<= 1) {
            n0 += __shfl_xor_sync(0xffffffffu, n0, m, 8);
            n1 += __shfl_xor_sync(0xffffffffu, n1, m, 8);
        }
        float inv0 = 1.0f / fmaxf(sqrtf(n0), 1e-12f);
        float inv1 = 1.0f / fmaxf(sqrtf(n1), 1e-12f);

        int grow0 = row_base + lrow0 + rp * 2;
        if (grow0 < N_NODES) {
            float* egp = &g_ego[(size_t)grow0 * EMB + jt * 8];
            reinterpret_cast<float4*>(egp)[0] = make_float4(a0[0], a0[1], a0[2], a0[3]);
            reinterpret_cast<float4*>(egp)[1] = make_float4(a0[4], a0[5], a0[6], a0[7]);
            float* alp = &g_all[(size_t)grow0 * OUT_EMB + (layer + 1) * EMB + jt * 8];
            reinterpret_cast<float4*>(alp)[0] =
                make_float4(a0[0] * inv0, a0[1] * inv0, a0[2] * inv0, a0[3] * inv0);
            reinterpret_cast<float4*>(alp)[1] =
                make_float4(a0[4] * inv0, a0[5] * inv0, a0[6] * inv0, a0[7] * inv0);
        }
        int grow1 = grow0 + 1;
        if (grow1 < N_NODES) {
            float* egp = &g_ego[(size_t)grow1 * EMB + jt * 8];
            reinterpret_cast<float4*>(egp)[0] = make_float4(a1[0], a1[1], a1[2], a1[3]);
            reinterpret_cast<float4*>(egp)[1] = make_float4(a1[4], a1[5], a1[6], a1[7]);
            float* alp = &g_all[(size_t)grow1 * OUT_EMB + (layer + 1) * EMB + jt * 8];
            reinterpret_cast<float4*>(alp)[0] =
                make_float4(a1[0] * inv1, a1[1] * inv1, a1[2] * inv1, a1[3] * inv1);
            reinterpret_cast<float4*>(alp)[1] =
                make_float4(a1[4] * inv1, a1[5] * inv1, a1[6] * inv1, a1[7] * inv1);
        }
    }
}

// ---------------------------------------------------------------------------
// Final gather: out = [ all[users], all[N_USER+pos], all[N_USER+neg] ]
// ---------------------------------------------------------------------------
__global__ __launch_bounds__(256) void k_gather(const int* __restrict__ users,
                                                const int* __restrict__ pos,
                                                const int* __restrict__ neg,
                                                float* __restrict__ out) {
    int t = blockIdx.x * blockDim.x + threadIdx.x;
    const int total = 3 * BATCH * (OUT_EMB / 4);
    if (t >= total) return;
    int g = t / (BATCH * (OUT_EMB / 4));
    int rem = t - g * (BATCH * (OUT_EMB / 4));
    int b = rem >> 6;          // OUT_EMB/4 = 64 float4 per row
    int f = rem & 63;
    int src;
    if (g == 0)      src = users[b];
    else if (g == 1) src = N_USER + pos[b];
    else             src = N_USER + neg[b];
    reinterpret_cast<float4*>(out)[t] =
        reinterpret_cast<const float4*>(&g_all[(size_t)src * OUT_EMB])[f];
}

// ---------------------------------------------------------------------------
extern "C" void kernel_launch(void* const* d_in, const int* in_sizes, int n_in,
                              void* d_out, int out_size) {
    const int*   users = (const int*)   d_in[0];
    const int*   pos   = (const int*)   d_in[1];
    const int*   neg   = (const int*)   d_in[2];
    const int*   arow  = (const int*)   d_in[3];
    const int*   acol  = (const int*)   d_in[4];
    const float* aval  = (const float*) d_in[5];
    const float* ue    = (const float*) d_in[6];
    const float* ie    = (const float*) d_in[7];
    const float* Wg    = (const float*) d_in[8];
    const float* bg    = (const float*) d_in[9];
    const float* Wb    = (const float*) d_in[10];
    const float* bb    = (const float*) d_in[11];
    float* out = (float*)d_out;

    k_init<<<(N_NODES * EMB / 4 + 255) / 256, 256>>>(ue, ie);

    // One-pass ELL build (no histogram, no scan) — amortized over 3 layers
    k_build<<<(NNZ + 255) / 256, 256>>>(arow, acol, aval);

    const int dense_grid = (N_NODES + DROWS - 1) / DROWS;
    for (int k = 0; k < N_LAYERS; k++) {
        k_spmm_ell<<<(N_NODES * 32 + 255) / 256, 256>>>();
        k_dense<<<dense_grid, 256>>>(Wg, bg, Wb, bb, k);
    }

    k_gather<<<(3 * BATCH * (OUT_EMB / 4) + 255) / 256, 256>>>(users, pos, neg, out);
}